// round 17
// baseline (speedup 1.0000x reference)
#include <cuda_runtime.h>
#include <cuda_bf16.h>
#include <cuda_fp16.h>
#include <math.h>
#include <stdint.h>

// Problem constants
#define B_SZ   4
#define T_SEQ  2048
#define DM     1024
#define NH     16
#define DH     64
#define WIN    256
#define M_ROWS (B_SZ * T_SEQ)        // 8192
#define N_QKV  (3 * DM)              // 3072

// fp16x1 GEMM tiling: 128x128x64 K-tiles, 128B smem rows,
// 4 warps (2x2 of 64x64), 2-stage ring, 3 CTAs/SM.
#define BM 128
#define BN 128
#define BKK 64
#define TILE_B (BM * 128)             // 16384 B per tile
#define NSTAGE 2
#define STG_B (2 * TILE_B)            // 32768 B (A + B)
#define GEMM_SMEM (NSTAGE * STG_B + 128)

// ---------------------------------------------------------------------------
// Device scratch (allocation-free per harness rules)
// ---------------------------------------------------------------------------
__device__ __align__(16) __half g_x16[M_ROWS * (size_t)DM];
__device__ __align__(16) __half g_wqkvT16[N_QKV * (size_t)DM];      // [N][K]
__device__ __align__(16) __half g_woutT16[DM * (size_t)DM];         // [N][K]
__device__ __align__(16) __half g_qkv16[M_ROWS * (size_t)N_QKV];    // fp16 QKV
__device__ __align__(16) __half g_att16[M_ROWS * (size_t)DM];       // attention out

// ---------------------------------------------------------------------------
// Helpers
// ---------------------------------------------------------------------------
__device__ __forceinline__ uint32_t smem_u32(const void* p) {
    return (uint32_t)__cvta_generic_to_shared(p);
}

#define CP16(saddr, gptr) \
    asm volatile("cp.async.cg.shared.global [%0], [%1], 16;" :: "r"(saddr), "l"(gptr))
#define CP16Z(saddr, gptr, sz) \
    asm volatile("cp.async.cg.shared.global [%0], [%1], 16, %2;" \
        :: "r"(saddr), "l"(gptr), "r"(sz))
#define CP_COMMIT() asm volatile("cp.async.commit_group;")
#define CP_WAIT(n)  asm volatile("cp.async.wait_group %0;" :: "n"(n))

#define LDM4(r, addr) \
    asm volatile("ldmatrix.sync.aligned.m8n8.x4.shared.b16 {%0,%1,%2,%3}, [%4];" \
        : "=r"((r)[0]), "=r"((r)[1]), "=r"((r)[2]), "=r"((r)[3]) : "r"(addr))

#define LDM4T(r, addr) \
    asm volatile("ldmatrix.sync.aligned.m8n8.x4.trans.shared.b16 {%0,%1,%2,%3}, [%4];" \
        : "=r"((r)[0]), "=r"((r)[1]), "=r"((r)[2]), "=r"((r)[3]) : "r"(addr))

#define MMA16816H(d, a, b0, b1) \
    asm volatile("mma.sync.aligned.m16n8k16.row.col.f32.f16.f16.f32 " \
        "{%0,%1,%2,%3}, {%4,%5,%6,%7}, {%8,%9}, {%0,%1,%2,%3};" \
        : "+f"((d)[0]), "+f"((d)[1]), "+f"((d)[2]), "+f"((d)[3]) \
        : "r"((a)[0]), "r"((a)[1]), "r"((a)[2]), "r"((a)[3]), "r"(b0), "r"(b1))

// 128B-row swizzle: 16B-chunk index XORed with (row & 7)
#define SWZ128(off) ((off) ^ ((((off) >> 7) & 7u) << 4))

// ---------------------------------------------------------------------------
// prep kernels
// ---------------------------------------------------------------------------
__global__ void cvt_f16_kernel(const float* __restrict__ src,
                               __half* __restrict__ dst, int n4) {
    int i = blockIdx.x * blockDim.x + threadIdx.x;
    if (i >= n4) return;
    float4 f = reinterpret_cast<const float4*>(src)[i];
    __half2 a = __half2(__float2half_rn(f.x), __float2half_rn(f.y));
    __half2 b = __half2(__float2half_rn(f.z), __float2half_rn(f.w));
    __half2* dp = reinterpret_cast<__half2*>(dst) + i * 2;
    dp[0] = a; dp[1] = b;
}

__global__ void transpose_f16_kernel(const float* __restrict__ src,
                                     __half* __restrict__ dst, int K, int N) {
    __shared__ float t[32][33];
    const int n0 = blockIdx.x * 32;
    const int k0 = blockIdx.y * 32;
    const int tx = threadIdx.x & 31;
    const int ty = threadIdx.x >> 5;
    #pragma unroll
    for (int i = 0; i < 32; i += 8)
        t[ty + i][tx] = src[(size_t)(k0 + ty + i) * N + n0 + tx];
    __syncthreads();
    #pragma unroll
    for (int i = 0; i < 32; i += 8)
        dst[(size_t)(n0 + ty + i) * K + k0 + tx] = __float2half_rn(t[tx][ty + i]);
}

// ---------------------------------------------------------------------------
// fp16x1 GEMM: C = A16 @ B16^T (Bt is [N][K]).
// 128x128x64 K-tiles, 4 warps (2M x 2N of 64x64), 2-stage ring, 3 CTAs/SM.
// Epilogue: C16!=null -> single fp16; else fp32 C.
// ---------------------------------------------------------------------------
__global__ __launch_bounds__(128, 3)
void gemm_f16(const __half* __restrict__ A16, const __half* __restrict__ Bq,
              float* __restrict__ C, __half* __restrict__ C16,
              int M, int N, int K) {
    extern __shared__ char smraw[];
    const uint32_t sbase = (smem_u32(smraw) + 127) & ~127u;

    const int tid  = threadIdx.x;
    const int lane = tid & 31;
    const int warp = tid >> 5;
    const int wm   = warp & 1;        // 0..1: 64 rows
    const int wn   = warp >> 1;       // 0..1: 64 cols
    const int m0   = blockIdx.y * BM;
    const int n0   = blockIdx.x * BN;

    float acc[4][8][4];               // [mt 16-row][nt 8-col][frag]
    #pragma unroll
    for (int a = 0; a < 4; a++)
        #pragma unroll
        for (int b = 0; b < 8; b++)
            #pragma unroll
            for (int c = 0; c < 4; c++) acc[a][b][c] = 0.f;

    const int NK = K / BKK;

    // loader: 2048 16B-chunks per stage (A 1024 + B 1024); 8 per tile per thread
    auto load_stage = [&](int buf, int kt) {
        const uint32_t s = sbase + buf * STG_B;
        const int kg = kt * BKK;
        #pragma unroll
        for (int i = 0; i < 8; ++i) {
            int cg  = tid + i * 128;
            int row = cg >> 3;
            int ck  = cg & 7;
            uint32_t so = SWZ128((uint32_t)(row * 128 + ck * 16));
            size_t ka = (size_t)kg + ck * 8;
            CP16(s + so,          A16 + (size_t)(m0 + row) * K + ka);
            CP16(s + TILE_B + so, Bq  + (size_t)(n0 + row) * K + ka);
        }
    };

    load_stage(0, 0); CP_COMMIT();

    const int a_r = wm * 64 + (lane & 15);
    const int a_c = (lane >> 4) << 4;
    const int b_r = wn * 64 + (lane & 7) + ((lane >> 4) << 3);
    const int b_c = ((lane >> 3) & 1) << 4;

    for (int kt = 0; kt < NK; ++kt) {
        CP_WAIT(0);          // stage kt resident
        __syncthreads();     // all warps finished stage kt-1 compute
        if (kt + 1 < NK) {   // prefetch kt+1 into the freed buffer
            load_stage((kt + 1) & 1, kt + 1);
            CP_COMMIT();
        }

        const uint32_t s = sbase + (kt & 1) * STG_B;
        #pragma unroll
        for (int ks = 0; ks < 4; ++ks) {
            uint32_t ah[4][4];
            #pragma unroll
            for (int mt = 0; mt < 4; ++mt) {
                uint32_t ro = SWZ128((uint32_t)((a_r + mt * 16) * 128 + ks * 32 + a_c));
                LDM4(ah[mt], s + ro);
            }
            #pragma unroll
            for (int np = 0; np < 4; ++np) {
                uint32_t ro = SWZ128((uint32_t)((b_r + np * 16) * 128 + ks * 32 + b_c));
                uint32_t bq[4];
                LDM4(bq, s + TILE_B + ro);
                #pragma unroll
                for (int mt = 0; mt < 4; ++mt) {
                    MMA16816H(acc[mt][2 * np],     ah[mt], bq[0], bq[1]);
                    MMA16816H(acc[mt][2 * np + 1], ah[mt], bq[2], bq[3]);
                }
            }
        }
    }

    if (C16 != nullptr) {
        #pragma unroll
        for (int mt = 0; mt < 4; ++mt) {
            #pragma unroll
            for (int nt = 0; nt < 8; ++nt) {
                int row = m0 + wm * 64 + mt * 16 + (lane >> 2);
                int col = n0 + wn * 64 + nt * 8 + (lane & 3) * 2;
                __half2 h0 = __half2(__float2half_rn(acc[mt][nt][0]),
                                     __float2half_rn(acc[mt][nt][1]));
                __half2 h1 = __half2(__float2half_rn(acc[mt][nt][2]),
                                     __float2half_rn(acc[mt][nt][3]));
                *reinterpret_cast<__half2*>(&C16[(size_t)row * N + col])       = h0;
                *reinterpret_cast<__half2*>(&C16[(size_t)(row + 8) * N + col]) = h1;
            }
        }
    } else {
        #pragma unroll
        for (int mt = 0; mt < 4; ++mt) {
            #pragma unroll
            for (int nt = 0; nt < 8; ++nt) {
                int row = m0 + wm * 64 + mt * 16 + (lane >> 2);
                int col = n0 + wn * 64 + nt * 8 + (lane & 3) * 2;
                float2 v0 = make_float2(acc[mt][nt][0], acc[mt][nt][1]);
                float2 v1 = make_float2(acc[mt][nt][2], acc[mt][nt][3]);
                *reinterpret_cast<float2*>(&C[(size_t)row * N + col]) = v0;
                *reinterpret_cast<float2*>(&C[(size_t)(row + 8) * N + col]) = v1;
            }
        }
    }
}

// ---------------------------------------------------------------------------
// Attention (all single-term fp16, unchanged from Round 16).
// ---------------------------------------------------------------------------
#define ATT_T 8192

__global__ __launch_bounds__(128, 4)
void attn_tc_kernel(const __half* __restrict__ qkv,
                    __half* __restrict__ out16) {
    extern __shared__ char smb[];
    const uint32_t sb = smem_u32(smb);
    const uint32_t sQ = sb;

    const int tid  = threadIdx.x;
    const int lane = tid & 31;
    const int warp = tid >> 5;
    const int q0 = blockIdx.x * 64;
    const int h  = blockIdx.y;
    const int b  = blockIdx.z;
    const int hoff = h * DH;
    const size_t rbase = (size_t)b * T_SEQ;

    const int c0 = (q0 >= 193) ? 0 : ((193 - q0 + 63) >> 6);

    auto load_kv = [&](int c) {
        const int kb = q0 - WIN + c * 64;
        const uint32_t sK = sb + (1 + 2 * (c & 1)) * ATT_T;
        const uint32_t sV = sK + ATT_T;
        #pragma unroll
        for (int i = 0; i < 4; i++) {
            int cg  = tid + i * 128;
            int row = cg >> 3;
            int ck  = cg & 7;
            int kg  = kb + row;
            uint32_t sz = (kg >= 0) ? 16u : 0u;
            int kgc = kg >= 0 ? kg : 0;
            uint32_t so = SWZ128((uint32_t)(row * 128 + ck * 16));
            size_t gk = (rbase + kgc) * N_QKV + DM + hoff + ck * 8;
            CP16Z(sK + so, qkv + gk, sz);
            CP16Z(sV + so, qkv + gk + DM, sz);
        }
    };

    #pragma unroll
    for (int i = 0; i < 4; i++) {
        int cg  = tid + i * 128;
        int row = cg >> 3;
        int ck  = cg & 7;
        uint32_t so = SWZ128((uint32_t)(row * 128 + ck * 16));
        size_t g = (rbase + q0 + row) * N_QKV + hoff + ck * 8;
        CP16(sQ + so, qkv + g);
    }
    CP_COMMIT();
    load_kv(c0);
    CP_COMMIT();

    float sa[8][4];
    float o[8][4];
    #pragma unroll
    for (int t = 0; t < 8; t++)
        #pragma unroll
        for (int j = 0; j < 4; j++) o[t][j] = 0.f;
    float m0 = -1e20f, m1 = -1e20f, l0 = 0.f, l1 = 0.f;

    const int lane2 = (lane & 3) * 2;
    const int qrow  = warp * 16 + (lane >> 2);
    const int qg0   = q0 + qrow;

    const int a_r = warp * 16 + (lane & 15);
    const int a_c = (lane >> 4) << 4;
    const int b_r = (lane & 7) + ((lane >> 4) << 3);
    const int b_c = ((lane >> 3) & 1) << 4;
    const int v_r = lane & 15;
    const int v_c = (lane >> 4) << 4;

    for (int c = c0; c < 5; c++) {
        const int kb = q0 - WIN + c * 64;
        CP_WAIT(0);
        __syncthreads();
        if (c + 1 < 5) {
            load_kv(c + 1);
            CP_COMMIT();
        }
        const uint32_t sKH = sb + (1 + 2 * (c & 1)) * ATT_T;
        const uint32_t sVH = sKH + ATT_T;

        #pragma unroll
        for (int t = 0; t < 8; t++)
            #pragma unroll
            for (int j = 0; j < 4; j++) sa[t][j] = 0.f;

        #pragma unroll
        for (int ks = 0; ks < 4; ks++) {
            uint32_t ah[4];
            uint32_t ao = SWZ128((uint32_t)(a_r * 128 + ks * 32 + a_c));
            LDM4(ah, sQ + ao);
            #pragma unroll
            for (int np = 0; np < 4; np++) {
                uint32_t bo = SWZ128((uint32_t)((np * 16 + b_r) * 128 + ks * 32 + b_c));
                uint32_t bk[4];
                LDM4(bk, sKH + bo);
                MMA16816H(sa[2 * np],     ah, bk[0], bk[1]);
                MMA16816H(sa[2 * np + 1], ah, bk[2], bk[3]);
            }
        }

        float mx0 = -1e30f, mx1 = -1e30f;
        #pragma unroll
        for (int t = 0; t < 8; t++) {
            #pragma unroll
            for (int j = 0; j < 4; j++) {
                int col = t * 8 + lane2 + (j & 1);
                int kg  = kb + col;
                int qg  = qg0 + ((j >> 1) << 3);
                bool valid = (kg >= 0) && (kg <= qg) && (kg >= qg - WIN);
                float s = valid ? sa[t][j] * 0.125f : -1e30f;
                sa[t][j] = s;
                if (j < 2) mx0 = fmaxf(mx0, s); else mx1 = fmaxf(mx1, s);
            }
        }
        mx0 = fmaxf(mx0, __shfl_xor_sync(0xffffffffu, mx0, 1));
        mx0 = fmaxf(mx0, __shfl_xor_sync(0xffffffffu, mx0, 2));
        mx1 = fmaxf(mx1, __shfl_xor_sync(0xffffffffu, mx1, 1));
        mx1 = fmaxf(mx1, __shfl_xor_sync(0xffffffffu, mx1, 2));

        const float mn0 = fmaxf(m0, mx0);
        const float mn1 = fmaxf(m1, mx1);
        const float sc0 = __expf(m0 - mn0);
        const float sc1 = __expf(m1 - mn1);
        m0 = mn0; m1 = mn1;

        float ps0 = 0.f, ps1 = 0.f;
        #pragma unroll
        for (int t = 0; t < 8; t++) {
            float p0 = __expf(sa[t][0] - mn0);
            float p1 = __expf(sa[t][1] - mn0);
            float p2 = __expf(sa[t][2] - mn1);
            float p3 = __expf(sa[t][3] - mn1);
            sa[t][0] = p0; sa[t][1] = p1; sa[t][2] = p2; sa[t][3] = p3;
            ps0 += p0 + p1; ps1 += p2 + p3;
        }
        ps0 += __shfl_xor_sync(0xffffffffu, ps0, 1);
        ps0 += __shfl_xor_sync(0xffffffffu, ps0, 2);
        ps1 += __shfl_xor_sync(0xffffffffu, ps1, 1);
        ps1 += __shfl_xor_sync(0xffffffffu, ps1, 2);
        l0 = l0 * sc0 + ps0;
        l1 = l1 * sc1 + ps1;

        #pragma unroll
        for (int t = 0; t < 8; t++) {
            o[t][0] *= sc0; o[t][1] *= sc0;
            o[t][2] *= sc1; o[t][3] *= sc1;
        }

        #pragma unroll
        for (int s = 0; s < 4; s++) {
            uint32_t aph[4];
            __half2 p01 = __half2(__float2half_rn(sa[2 * s][0]),     __float2half_rn(sa[2 * s][1]));
            __half2 p23 = __half2(__float2half_rn(sa[2 * s][2]),     __float2half_rn(sa[2 * s][3]));
            __half2 p45 = __half2(__float2half_rn(sa[2 * s + 1][0]), __float2half_rn(sa[2 * s + 1][1]));
            __half2 p67 = __half2(__float2half_rn(sa[2 * s + 1][2]), __float2half_rn(sa[2 * s + 1][3]));
            aph[0] = *reinterpret_cast<uint32_t*>(&p01);
            aph[1] = *reinterpret_cast<uint32_t*>(&p23);
            aph[2] = *reinterpret_cast<uint32_t*>(&p45);
            aph[3] = *reinterpret_cast<uint32_t*>(&p67);
            #pragma unroll
            for (int nd = 0; nd < 4; nd++) {
                uint32_t vo = SWZ128((uint32_t)((s * 16 + v_r) * 128 + nd * 32 + v_c));
                uint32_t vv[4];
                LDM4T(vv, sVH + vo);
                MMA16816H(o[2 * nd],     aph, vv[0], vv[1]);
                MMA16816H(o[2 * nd + 1], aph, vv[2], vv[3]);
            }
        }
    }

    const float il0 = 1.f / l0;
    const float il1 = 1.f / l1;
    const size_t row0 = rbase + qg0;
    #pragma unroll
    for (int t = 0; t < 8; t++) {
        int col = hoff + t * 8 + lane2;
        __half2 h0 = __half2(__float2half_rn(o[t][0] * il0), __float2half_rn(o[t][1] * il0));
        __half2 h1 = __half2(__float2half_rn(o[t][2] * il1), __float2half_rn(o[t][3] * il1));
        *reinterpret_cast<__half2*>(&out16[row0 * DM + col])       = h0;
        *reinterpret_cast<__half2*>(&out16[(row0 + 8) * DM + col]) = h1;
    }
}

// ---------------------------------------------------------------------------
extern "C" void kernel_launch(void* const* d_in, const int* in_sizes, int n_in,
                              void* d_out, int out_size) {
    const float* x     = (const float*)d_in[0];
    const float* w_qkv = (const float*)d_in[1];
    const float* w_out = (const float*)d_in[2];
    float* out = (float*)d_out;

    __half *x16, *wq16, *wo16, *at16, *qkv16;
    cudaGetSymbolAddress((void**)&x16,   g_x16);
    cudaGetSymbolAddress((void**)&wq16,  g_wqkvT16);
    cudaGetSymbolAddress((void**)&wo16,  g_woutT16);
    cudaGetSymbolAddress((void**)&qkv16, g_qkv16);
    cudaGetSymbolAddress((void**)&at16,  g_att16);

    cudaFuncSetAttribute(gemm_f16, cudaFuncAttributeMaxDynamicSharedMemorySize, GEMM_SMEM);
    const int ATTN_SMEM = 5 * ATT_T;   // 40 KB
    cudaFuncSetAttribute(attn_tc_kernel, cudaFuncAttributeMaxDynamicSharedMemorySize, ATTN_SMEM);

    // 0) prep: x -> fp16; w_qkv, w_out -> [N][K] fp16
    {
        int n4 = M_ROWS * DM / 4;
        cvt_f16_kernel<<<(n4 + 255) / 256, 256>>>(x, x16, n4);
        dim3 g1(N_QKV / 32, DM / 32);
        transpose_f16_kernel<<<g1, 256>>>(w_qkv, wq16, DM, N_QKV);
        dim3 g2(DM / 32, DM / 32);
        transpose_f16_kernel<<<g2, 256>>>(w_out, wo16, DM, DM);
    }
    // 1) QKV projection (fp16x1) -> single fp16
    {
        dim3 grid(N_QKV / BN, M_ROWS / BM);
        gemm_f16<<<grid, 128, GEMM_SMEM>>>(x16, wq16, nullptr, qkv16,
                                           M_ROWS, N_QKV, DM);
    }
    // 2) attention
    {
        dim3 grid(T_SEQ / 64, NH, B_SZ);
        attn_tc_kernel<<<grid, 128, ATTN_SMEM>>>(qkv16, at16);
    }
    // 3) output projection (fp16x1) -> fp32
    {
        dim3 grid(DM / BN, M_ROWS / BM);
        gemm_f16<<<grid, 128, GEMM_SMEM>>>(at16, wo16, out, nullptr,
                                           M_ROWS, DM, DM);
    }
}